// round 14
// baseline (speedup 1.0000x reference)
#include <cuda_runtime.h>
#include <cuda_fp16.h>
#include <cstdint>
#include <math.h>

#define DIM 128
#define SHALF 8192
#define LDH 136                 // halves per smem row (16B-phase conflict-free)
#define TILE_H (128 * LDH)      // halves per tile (17408)
#define TILE_B (TILE_H * 2)     // 34816 bytes per tile
#define LDF 132                 // f32 leading dim for prep

// Device scratch (no cudaMalloc allowed)
// g_Mt[n][k]  = sum_d Wk[n,d]*Wq[k,d]/sqrt(D)   (fp16)
// g_W2t[j][k] = sum_d Wv[k,d]*Wo[d,j]           (fp16)
__device__ __half g_Mt[DIM * DIM];
__device__ __half g_W2t[DIM * DIM];
__device__ unsigned g_flag;     // prep-done gate (monotone across launches)

__device__ __forceinline__ uint32_t smem_u32(const void* p) {
    uint32_t a;
    asm("{ .reg .u64 t; cvta.to.shared.u64 t, %1; cvt.u32.u64 %0, t; }" : "=r"(a) : "l"(p));
    return a;
}
__device__ __forceinline__ float gelu_erf(float y) {
    return 0.5f * y * (1.0f + erff(y * 0.70710678118654752440f));
}
__device__ __forceinline__ void ldsm4(uint32_t r[4], uint32_t a) {
    asm volatile("ldmatrix.sync.aligned.m8n8.x4.shared.b16 {%0,%1,%2,%3}, [%4];"
                 : "=r"(r[0]), "=r"(r[1]), "=r"(r[2]), "=r"(r[3]) : "r"(a));
}
__device__ __forceinline__ void ldsm4t(uint32_t r[4], uint32_t a) {
    asm volatile("ldmatrix.sync.aligned.m8n8.x4.trans.shared.b16 {%0,%1,%2,%3}, [%4];"
                 : "=r"(r[0]), "=r"(r[1]), "=r"(r[2]), "=r"(r[3]) : "r"(a));
}
__device__ __forceinline__ void mma_h(float c[4], const uint32_t a[4],
                                      uint32_t b0, uint32_t b1) {
    asm volatile(
        "mma.sync.aligned.m16n8k16.row.col.f32.f16.f16.f32 "
        "{%0,%1,%2,%3}, {%4,%5,%6,%7}, {%8,%9}, {%0,%1,%2,%3};"
        : "+f"(c[0]), "+f"(c[1]), "+f"(c[2]), "+f"(c[3])
        : "r"(a[0]), "r"(a[1]), "r"(a[2]), "r"(a[3]), "r"(b0), "r"(b1));
}

// 128x128x128 fp16 GEMM, 8 warps (wm=wid&3: 32 rows; wn=wid>>2: 64 cols).
// BT=0: B is [n][k] row-major in smem (plain LDSM). BT=1: B is [k][n] (LDSM.trans).
template <int BT>
__device__ __forceinline__ void gemm_h(uint32_t aAddr, uint32_t bAddr,
                                       float acc[2][8][4]) {
#pragma unroll
    for (int kk = 0; kk < 8; kk++) {
        uint32_t a0[4], a1[4];
        ldsm4(a0, aAddr + kk * 32);
        ldsm4(a1, aAddr + 16 * LDH * 2 + kk * 32);
#pragma unroll
        for (int p = 0; p < 4; p++) {
            uint32_t b[4];
            if (BT) ldsm4t(b, bAddr + p * 32 + kk * (16 * LDH * 2));
            else    ldsm4 (b, bAddr + p * (16 * LDH * 2) + kk * 32);
            mma_h(acc[0][2 * p],     a0, b[0], b[1]);
            mma_h(acc[0][2 * p + 1], a0, b[2], b[3]);
            mma_h(acc[1][2 * p],     a1, b[0], b[1]);
            mma_h(acc[1][2 * p + 1], a1, b[2], b[3]);
        }
    }
}

__device__ __forceinline__ void zero_acc(float acc[2][8][4]) {
#pragma unroll
    for (int mi = 0; mi < 2; mi++)
#pragma unroll
        for (int j = 0; j < 8; j++)
#pragma unroll
            for (int e = 0; e < 4; e++) acc[mi][j][e] = 0.f;
}

// Store acc (fp16) to Ch at warp tile position.
__device__ __forceinline__ void store_c(__half* Ch, const float acc[2][8][4],
                                        int wm, int wn, int lane) {
    __half* base = Ch + (wm * 32 + (lane >> 2)) * LDH + wn * 64 + 2 * (lane & 3);
#pragma unroll
    for (int mi = 0; mi < 2; mi++)
#pragma unroll
        for (int j = 0; j < 8; j++) {
            *(__half2*)(base + mi * 16 * LDH + j * 8) =
                __floats2half2_rn(acc[mi][j][0], acc[mi][j][1]);
            *(__half2*)(base + mi * 16 * LDH + 8 * LDH + j * 8) =
                __floats2half2_rn(acc[mi][j][2], acc[mi][j][3]);
        }
}

// ---------------------------------------------------------------------------
// Fused persistent kernel, 256 threads, 2 CTAs/SM, grid = nAttn (all wave-1).
// bid<32: do prep FIRST, then join the persistent attn loop.
// smem: Xh | W2 (resident W2t) | Sh (Mt -> P -> S -> attn -> T)
// Next-block X prefetched into Xh during T-store/G4 (Xh dead after G3 reads).
// ---------------------------------------------------------------------------
__global__ void __launch_bounds__(256, 2)
fused_kernel(const float* __restrict__ x,
             const float* __restrict__ Wq, const float* __restrict__ Wk,
             const float* __restrict__ Wv, const float* __restrict__ Wo,
             const float* __restrict__ gamma, const float* __restrict__ beta,
             float* __restrict__ out, int nBlk, int nAttn) {
    extern __shared__ __align__(16) char smraw[];
    const int tid = threadIdx.x, bid = blockIdx.x;

    // ===================== PREP (bid < 32), then fall through =============
    if (bid < 32) {
        float* BigT = (float*)smraw;            // [128][LDF]
        float* Sm = BigT + 128 * LDF;           // 1024 floats
        const bool modeM = bid < 16;
        const int strip = (bid & 15) * 8;

        if (modeM) {
            for (int i = tid; i < 16384; i += 256) {
                int k = i >> 7, d = i & 127;
                BigT[d * LDF + k] = Wq[i];                 // BigT[d][k] = Wq[k][d]
            }
            for (int i = tid; i < 1024; i += 256) {
                int n = i >> 7, d = i & 127;
                Sm[i] = Wk[(strip + n) * DIM + d];
            }
        } else {
            for (int i = tid; i < 16384; i += 256) {
                int k = i >> 7, d = i & 127;
                BigT[d * LDF + k] = Wv[i];                 // BigT[d][k] = Wv[k][d]
            }
            for (int i = tid; i < 1024; i += 256) {
                int d = i >> 3, j = i & 7;
                Sm[i] = Wo[d * DIM + strip + j];
            }
        }
        __syncthreads();

        const int row = tid >> 5, k0 = (tid & 31) << 2;
        float4 acc = make_float4(0.f, 0.f, 0.f, 0.f);
#pragma unroll 4
        for (int d = 0; d < 128; d++) {
            float s = modeM ? Sm[row * DIM + d] : Sm[d * 8 + row];
            float4 v = *(const float4*)(BigT + d * LDF + k0);
            acc.x += s * v.x; acc.y += s * v.y; acc.z += s * v.z; acc.w += s * v.w;
        }
        const float sc = modeM ? 0.08838834764831844055f : 1.0f;
        __half2 p0 = __floats2half2_rn(acc.x * sc, acc.y * sc);
        __half2 p1 = __floats2half2_rn(acc.z * sc, acc.w * sc);
        __half* dst = (modeM ? g_Mt : g_W2t) + (strip + row) * DIM + k0;
        *(__half2*)(dst) = p0;
        *(__half2*)(dst + 2) = p1;

        __syncthreads();                        // prep smem reads done
        if (tid == 0) {
            __threadfence();
            atomicAdd(&g_flag, 1u);
        }
        // fall through into attn
    }

    // ===================== ATTN (persistent, all CTAs) ====================
    __half* Xh = (__half*)smraw;          // X [token][dim]
    __half* W2 = Xh + TILE_H;             // W2t [n][k] (resident)
    __half* Sh = W2 + TILE_H;             // Mt -> P -> S -> attn -> T
    __shared__ float s_r1[128][2], s_r2[128][2], s_g[DIM], s_b[DIM];

    const int lane = tid & 31, wid = tid >> 5;
    const int wm = wid & 3, wn = wid >> 2;
    const int g4 = lane >> 2;

    if (tid < DIM) { s_g[tid] = gamma[tid]; s_b[tid] = beta[tid]; }

    // gelu(beta) broadcast chunk for mirror fill (registers, loop-invariant)
    const int mc4 = (tid & 31) << 2, mr0 = tid >> 5;
    float4 gb;
    gb.x = gelu_erf(beta[mc4 + 0]);
    gb.y = gelu_erf(beta[mc4 + 1]);
    gb.z = gelu_erf(beta[mc4 + 2]);
    gb.w = gelu_erf(beta[mc4 + 3]);

    // X loader: f32 gmem -> fp16 smem (Xh)
    auto loadX = [&](int blkIdx) {
        const int batch = blkIdx >> 6, blk = blkIdx & 63;
        const float4* Xg4 =
            (const float4*)(x + ((size_t)batch * SHALF + (size_t)blk * 128) * DIM);
        for (int i = tid; i < 4096; i += 256) {
            int r = i >> 5, c4 = (i & 31) << 2;
            float4 v = Xg4[i];
            *(__half2*)(Xh + r * LDH + c4) = __floats2half2_rn(v.x, v.y);
            *(__half2*)(Xh + r * LDH + c4 + 2) = __floats2half2_rn(v.z, v.w);
        }
    };

    // Gate on prep (first launch only; values rewritten byte-identical after).
    // All grid CTAs are wave-1 resident (grid == nAttn <= 2*SMs), no deadlock.
    if (tid == 0) {
        while (atomicAdd(&g_flag, 0u) < 32u) __nanosleep(128);
        __threadfence();
    }
    __syncthreads();      // gate visible; prep CTAs: smem safe to overwrite

    // Initial X load for first owned block
    if (bid < nBlk) loadX(bid);

    // Stage W2t once (resident; first read is G4, many barriers away)
    {
        const uint4* W4 = (const uint4*)g_W2t;
        for (int i = tid; i < 2048; i += 256) {
            int r = i >> 4, c8 = (i & 15) << 3;
            *(uint4*)(W2 + r * LDH + c8) = W4[i];
        }
    }

    // Lane-resolved LDSM byte addresses (loop-invariant)
    const uint32_t xAddr = smem_u32(Xh), wAddr = smem_u32(W2), sAddr = smem_u32(Sh);
    const uint32_t aLane = ((wm * 32 + (lane & 15)) * LDH + ((lane >> 4) << 3)) * 2;
    const uint32_t bpLane = (((lane & 7) + ((lane >> 4) << 3) + wn * 64) * LDH + (lane & 8)) * 2;
    const uint32_t btLane = ((lane & 15) * LDH + wn * 64 + ((lane >> 4) << 3)) * 2;

    float acc[2][8][4];

    for (int blkIdx = bid; blkIdx < nBlk; blkIdx += nAttn) {
        const int batch = blkIdx >> 6, blk = blkIdx & 63;

        // Stage Mt into Sh (overwritten in-place by P)
        {
            const uint4* M4 = (const uint4*)g_Mt;
            for (int i = tid; i < 2048; i += 256) {
                int r = i >> 4, c8 = (i & 15) << 3;
                *(uint4*)(Sh + r * LDH + c8) = M4[i];
            }
        }
        __syncthreads();   // Mt + X (initial or prefetched) visible

        // G1: P = X @ Mt^T  (A=Xh, B=Sh plain); P overwrites Mt in Sh
        zero_acc(acc);
        gemm_h<0>(xAddr + aLane, sAddr + bpLane, acc);
        __syncthreads();                 // all warps done reading Mt
        store_c(Sh, acc, wm, wn, lane);
        __syncthreads();

        // G2: S = P @ X^T  (A=Sh, B=Xh plain), in place over P
        zero_acc(acc);
        gemm_h<0>(sAddr + aLane, xAddr + bpLane, acc);
        __syncthreads();
        store_c(Sh, acc, wm, wn, lane);
        __syncthreads();

        // Softmax: 2 threads per row, 64 cols each, fp16 in/out
        {
            const int row = tid >> 1, h = tid & 1;
            __half* rp = Sh + row * LDH + h * 64;
            float f[64];
#pragma unroll
            for (int i = 0; i < 8; i++) {
                uint4 v = *(uint4*)(rp + 8 * i);
                float2 p0 = __half22float2(*(__half2*)&v.x);
                float2 p1 = __half22float2(*(__half2*)&v.y);
                float2 p2 = __half22float2(*(__half2*)&v.z);
                float2 p3 = __half22float2(*(__half2*)&v.w);
                f[8 * i + 0] = p0.x; f[8 * i + 1] = p0.y;
                f[8 * i + 2] = p1.x; f[8 * i + 3] = p1.y;
                f[8 * i + 4] = p2.x; f[8 * i + 5] = p2.y;
                f[8 * i + 6] = p3.x; f[8 * i + 7] = p3.y;
            }
            float m = -1e30f;
#pragma unroll
            for (int i = 0; i < 64; i++) m = fmaxf(m, f[i]);
            m = fmaxf(m, __shfl_xor_sync(0xffffffffu, m, 1));
            float s = 0.f;
#pragma unroll
            for (int i = 0; i < 64; i++) { f[i] = __expf(f[i] - m); s += f[i]; }
            s += __shfl_xor_sync(0xffffffffu, s, 1);
            float inv = 1.0f / s;
#pragma unroll
            for (int i = 0; i < 8; i++) {
                uint4 v;
                *(__half2*)&v.x = __floats2half2_rn(f[8 * i + 0] * inv, f[8 * i + 1] * inv);
                *(__half2*)&v.y = __floats2half2_rn(f[8 * i + 2] * inv, f[8 * i + 3] * inv);
                *(__half2*)&v.z = __floats2half2_rn(f[8 * i + 4] * inv, f[8 * i + 5] * inv);
                *(__half2*)&v.w = __floats2half2_rn(f[8 * i + 6] * inv, f[8 * i + 7] * inv);
                *(uint4*)(rp + 8 * i) = v;
            }
        }
        __syncthreads();

        // G3: T = attn @ X  (A=Sh, B=Xh TRANS), in place over attn
        zero_acc(acc);
        gemm_h<1>(sAddr + aLane, xAddr + btLane, acc);
        __syncthreads();                 // Xh reads done -> Xh is dead

        // Store T; overlap: prefetch NEXT block's X into Xh (independent regions)
        store_c(Sh, acc, wm, wn, lane);
        {
            int next = blkIdx + nAttn;
            if (next < nBlk) loadX(next);
        }
        __syncthreads();

        // G4: H = T @ W2t^T (A=Sh, B=W2 plain), accumulators stay in registers
        zero_acc(acc);
        gemm_h<0>(sAddr + aLane, wAddr + bpLane, acc);

        // LN partials
#pragma unroll
        for (int mi = 0; mi < 2; mi++)
#pragma unroll
            for (int h = 0; h < 2; h++) {
                float s1 = 0.f, s2 = 0.f;
#pragma unroll
                for (int j = 0; j < 8; j++) {
                    float v0 = acc[mi][j][2 * h], v1 = acc[mi][j][2 * h + 1];
                    s1 += v0 + v1;
                    s2 += v0 * v0 + v1 * v1;
                }
                s1 += __shfl_xor_sync(0xffffffffu, s1, 1);
                s1 += __shfl_xor_sync(0xffffffffu, s1, 2);
                s2 += __shfl_xor_sync(0xffffffffu, s2, 1);
                s2 += __shfl_xor_sync(0xffffffffu, s2, 2);
                if ((lane & 3) == 0) {
                    int r = wm * 32 + mi * 16 + 8 * h + g4;
                    s_r1[r][wn] = s1;
                    s_r2[r][wn] = s2;
                }
            }
        __syncthreads();

        // Epilogue: LN + exact GELU from registers; plus mirror-half fill
        float* ob = out + ((size_t)batch * 2 * SHALF + (size_t)blk * 128) * DIM;
#pragma unroll
        for (int mi = 0; mi < 2; mi++)
#pragma unroll
            for (int h = 0; h < 2; h++) {
                const int r = wm * 32 + mi * 16 + 8 * h + g4;
                float s1 = s_r1[r][0] + s_r1[r][1];
                float s2 = s_r2[r][0] + s_r2[r][1];
                float mu = s1 * (1.0f / 128.0f);
                float var = s2 * (1.0f / 128.0f) - mu * mu;
                float rs = rsqrtf(var + 1e-5f);
                float* orow = ob + (size_t)r * DIM;
#pragma unroll
                for (int j = 0; j < 8; j++) {
                    const int c = wn * 64 + j * 8 + 2 * (lane & 3);
                    float2 o;
                    o.x = gelu_erf((acc[mi][j][2 * h] - mu) * rs * s_g[c] + s_b[c]);
                    o.y = gelu_erf((acc[mi][j][2 * h + 1] - mu) * rs * s_g[c + 1] + s_b[c + 1]);
                    *(float2*)(orow + c) = o;
                }
            }
        {
            float* mb = out + ((size_t)batch * 2 * SHALF + SHALF + (size_t)blk * 128) * DIM;
#pragma unroll
            for (int j = 0; j < 16; j++)
                *(float4*)(mb + (size_t)(mr0 + 8 * j) * DIM + mc4) = gb;
        }
        __syncthreads();   // Sh/s_r reuse next iteration
    }
}

extern "C" void kernel_launch(void* const* d_in, const int* in_sizes, int n_in,
                              void* d_out, int out_size) {
    const float* x     = (const float*)d_in[0];
    const float* Wq    = (const float*)d_in[1];
    const float* Wk    = (const float*)d_in[2];
    const float* Wv    = (const float*)d_in[3];
    const float* Wo    = (const float*)d_in[4];
    const float* gamma = (const float*)d_in[5];
    const float* beta  = (const float*)d_in[6];
    float* out = (float*)d_out;

    int B = in_sizes[0] / (SHALF * DIM);  // 8
    int nBlk = B * 64;                    // 512

    int dev = 0, sms = 148;
    cudaGetDevice(&dev);
    cudaDeviceGetAttribute(&sms, cudaDevAttrMultiProcessorCount, dev);
    int nAttn = 2 * sms;                  // all wave-1 resident (2 CTAs/SM)
    if (nAttn > nBlk) nAttn = nBlk;
    if (nAttn < 32) nAttn = 32;           // prep needs 32 CTAs

    const int smem_bytes = 3 * TILE_B;    // 104448
    cudaFuncSetAttribute(fused_kernel, cudaFuncAttributeMaxDynamicSharedMemorySize,
                         smem_bytes);
    fused_kernel<<<nAttn, 256, smem_bytes>>>(x, Wq, Wk, Wv, Wo, gamma, beta,
                                             out, nBlk, nAttn);
}

// round 15
// speedup vs baseline: 1.6814x; 1.6814x over previous
#include <cuda_runtime.h>
#include <cuda_fp16.h>
#include <cstdint>
#include <math.h>

#define DIM 128
#define SHALF 8192
#define LDH 136                 // halves per smem row (16B-phase conflict-free)
#define TILE_H (128 * LDH)      // halves per tile (17408)
#define TILE_B (TILE_H * 2)     // 34816 bytes per tile
#define LDF 132                 // f32 leading dim for prep

// Device scratch (no cudaMalloc allowed)
// g_Mt[n][k]  = sum_d Wk[n,d]*Wq[k,d]/sqrt(D)   (fp16)
// g_W2t[j][k] = sum_d Wv[k,d]*Wo[d,j]           (fp16)
__device__ __half g_Mt[DIM * DIM];
__device__ __half g_W2t[DIM * DIM];
__device__ unsigned g_flag;     // prep-done gate (monotone across launches)

__device__ __forceinline__ uint32_t smem_u32(const void* p) {
    uint32_t a;
    asm("{ .reg .u64 t; cvta.to.shared.u64 t, %1; cvt.u32.u64 %0, t; }" : "=r"(a) : "l"(p));
    return a;
}
__device__ __forceinline__ float gelu_erf(float y) {
    return 0.5f * y * (1.0f + erff(y * 0.70710678118654752440f));
}
__device__ __forceinline__ void cpasync16(uint32_t smem_dst, const void* gmem_src) {
    asm volatile("cp.async.cg.shared.global [%0], [%1], 16;"
                 :: "r"(smem_dst), "l"(gmem_src) : "memory");
}
__device__ __forceinline__ void cpasync_commit() {
    asm volatile("cp.async.commit_group;" ::: "memory");
}
__device__ __forceinline__ void cpasync_wait0() {
    asm volatile("cp.async.wait_group 0;" ::: "memory");
}
__device__ __forceinline__ void ldsm4(uint32_t r[4], uint32_t a) {
    asm volatile("ldmatrix.sync.aligned.m8n8.x4.shared.b16 {%0,%1,%2,%3}, [%4];"
                 : "=r"(r[0]), "=r"(r[1]), "=r"(r[2]), "=r"(r[3]) : "r"(a));
}
__device__ __forceinline__ void ldsm4t(uint32_t r[4], uint32_t a) {
    asm volatile("ldmatrix.sync.aligned.m8n8.x4.trans.shared.b16 {%0,%1,%2,%3}, [%4];"
                 : "=r"(r[0]), "=r"(r[1]), "=r"(r[2]), "=r"(r[3]) : "r"(a));
}
__device__ __forceinline__ void mma_h(float c[4], const uint32_t a[4],
                                      uint32_t b0, uint32_t b1) {
    asm volatile(
        "mma.sync.aligned.m16n8k16.row.col.f32.f16.f16.f32 "
        "{%0,%1,%2,%3}, {%4,%5,%6,%7}, {%8,%9}, {%0,%1,%2,%3};"
        : "+f"(c[0]), "+f"(c[1]), "+f"(c[2]), "+f"(c[3])
        : "r"(a[0]), "r"(a[1]), "r"(a[2]), "r"(a[3]), "r"(b0), "r"(b1));
}

// 128x128x128 fp16 GEMM, 8 warps (wm=wid&3: 32 rows; wn=wid>>2: 64 cols).
// BT=0: B is [n][k] row-major in smem (plain LDSM). BT=1: B is [k][n] (LDSM.trans).
template <int BT>
__device__ __forceinline__ void gemm_h(uint32_t aAddr, uint32_t bAddr,
                                       float acc[2][8][4]) {
#pragma unroll
    for (int kk = 0; kk < 8; kk++) {
        uint32_t a0[4], a1[4];
        ldsm4(a0, aAddr + kk * 32);
        ldsm4(a1, aAddr + 16 * LDH * 2 + kk * 32);
#pragma unroll
        for (int p = 0; p < 4; p++) {
            uint32_t b[4];
            if (BT) ldsm4t(b, bAddr + p * 32 + kk * (16 * LDH * 2));
            else    ldsm4 (b, bAddr + p * (16 * LDH * 2) + kk * 32);
            mma_h(acc[0][2 * p],     a0, b[0], b[1]);
            mma_h(acc[0][2 * p + 1], a0, b[2], b[3]);
            mma_h(acc[1][2 * p],     a1, b[0], b[1]);
            mma_h(acc[1][2 * p + 1], a1, b[2], b[3]);
        }
    }
}

__device__ __forceinline__ void zero_acc(float acc[2][8][4]) {
#pragma unroll
    for (int mi = 0; mi < 2; mi++)
#pragma unroll
        for (int j = 0; j < 8; j++)
#pragma unroll
            for (int e = 0; e < 4; e++) acc[mi][j][e] = 0.f;
}

// Store acc (fp16) to Ch at warp tile position.
__device__ __forceinline__ void store_c(__half* Ch, const float acc[2][8][4],
                                        int wm, int wn, int lane) {
    __half* base = Ch + (wm * 32 + (lane >> 2)) * LDH + wn * 64 + 2 * (lane & 3);
#pragma unroll
    for (int mi = 0; mi < 2; mi++)
#pragma unroll
        for (int j = 0; j < 8; j++) {
            *(__half2*)(base + mi * 16 * LDH + j * 8) =
                __floats2half2_rn(acc[mi][j][0], acc[mi][j][1]);
            *(__half2*)(base + mi * 16 * LDH + 8 * LDH + j * 8) =
                __floats2half2_rn(acc[mi][j][2], acc[mi][j][3]);
        }
}

// ---------------------------------------------------------------------------
// Fused kernel, 256 threads, 2 CTAs/SM. bid<32: prep. bid>=32: persistent
// attn CTA looping over blocks (stride nAttn).
// smem: Xh | W2 (resident W2t) | Sh (Mt -> P -> S -> attn -> T)
// Weight staging via cp.async (no register round-trip; overlaps X load).
// ---------------------------------------------------------------------------
__global__ void __launch_bounds__(256, 2)
fused_kernel(const float* __restrict__ x,
             const float* __restrict__ Wq, const float* __restrict__ Wk,
             const float* __restrict__ Wv, const float* __restrict__ Wo,
             const float* __restrict__ gamma, const float* __restrict__ beta,
             float* __restrict__ out, int nBlk, int nAttn) {
    extern __shared__ __align__(16) char smraw[];
    const int tid = threadIdx.x, bid = blockIdx.x;

    // ===================== PREP CTAs =====================
    if (bid < 32) {
        float* BigT = (float*)smraw;            // [128][LDF]
        float* Sm = BigT + 128 * LDF;           // 1024 floats
        const bool modeM = bid < 16;
        const int strip = (bid & 15) * 8;

        if (modeM) {
            for (int i = tid; i < 16384; i += 256) {
                int k = i >> 7, d = i & 127;
                BigT[d * LDF + k] = Wq[i];                 // BigT[d][k] = Wq[k][d]
            }
            for (int i = tid; i < 1024; i += 256) {
                int n = i >> 7, d = i & 127;
                Sm[i] = Wk[(strip + n) * DIM + d];
            }
        } else {
            for (int i = tid; i < 16384; i += 256) {
                int k = i >> 7, d = i & 127;
                BigT[d * LDF + k] = Wv[i];                 // BigT[d][k] = Wv[k][d]
            }
            for (int i = tid; i < 1024; i += 256) {
                int d = i >> 3, j = i & 7;
                Sm[i] = Wo[d * DIM + strip + j];
            }
        }
        __syncthreads();

        const int row = tid >> 5, k0 = (tid & 31) << 2;
        float4 acc = make_float4(0.f, 0.f, 0.f, 0.f);
#pragma unroll 4
        for (int d = 0; d < 128; d++) {
            float s = modeM ? Sm[row * DIM + d] : Sm[d * 8 + row];
            float4 v = *(const float4*)(BigT + d * LDF + k0);
            acc.x += s * v.x; acc.y += s * v.y; acc.z += s * v.z; acc.w += s * v.w;
        }
        const float sc = modeM ? 0.08838834764831844055f : 1.0f;
        __half2 p0 = __floats2half2_rn(acc.x * sc, acc.y * sc);
        __half2 p1 = __floats2half2_rn(acc.z * sc, acc.w * sc);
        __half* dst = (modeM ? g_Mt : g_W2t) + (strip + row) * DIM + k0;
        *(__half2*)(dst) = p0;
        *(__half2*)(dst + 2) = p1;

        __syncthreads();
        if (tid == 0) {
            __threadfence();
            atomicAdd(&g_flag, 1u);
        }
        return;
    }

    // ===================== ATTN CTAs (persistent) =====================
    __half* Xh = (__half*)smraw;          // X [token][dim]
    __half* W2 = Xh + TILE_H;             // W2t [n][k] (resident)
    __half* Sh = W2 + TILE_H;             // Mt -> P -> S -> attn -> T
    __shared__ float s_r1[128][2], s_r2[128][2], s_g[DIM], s_b[DIM];

    const int lane = tid & 31, wid = tid >> 5;
    const int wm = wid & 3, wn = wid >> 2;
    const int g4 = lane >> 2;

    if (tid < DIM) { s_g[tid] = gamma[tid]; s_b[tid] = beta[tid]; }

    // Precompute gelu(beta) broadcast row chunk for mirror fill (registers)
    const int mc4 = (tid & 31) << 2, mr0 = tid >> 5;
    float4 gb;
    gb.x = gelu_erf(beta[mc4 + 0]);
    gb.y = gelu_erf(beta[mc4 + 1]);
    gb.z = gelu_erf(beta[mc4 + 2]);
    gb.w = gelu_erf(beta[mc4 + 3]);

    // Gate on prep (first launch only; values rewritten byte-identical after).
    if (tid == 0) {
        while (atomicAdd(&g_flag, 0u) < 32u) __nanosleep(128);
        __threadfence();
    }
    __syncthreads();

    const uint32_t xAddr = smem_u32(Xh), wAddr = smem_u32(W2), sAddr = smem_u32(Sh);

    // Stage W2t once via cp.async (resident for the whole persistent loop)
    {
        const char* W4 = (const char*)g_W2t;
        for (int i = tid; i < 2048; i += 256) {
            int r = i >> 4, c8 = (i & 15) << 3;
            cpasync16(wAddr + (r * LDH + c8) * 2, W4 + i * 16);
        }
        cpasync_commit();
        cpasync_wait0();
    }

    // Lane-resolved LDSM byte addresses (loop-invariant)
    const uint32_t aLane = ((wm * 32 + (lane & 15)) * LDH + ((lane >> 4) << 3)) * 2;
    const uint32_t bpLane = (((lane & 7) + ((lane >> 4) << 3) + wn * 64) * LDH + (lane & 8)) * 2;
    const uint32_t btLane = ((lane & 15) * LDH + wn * 64 + ((lane >> 4) << 3)) * 2;

    float acc[2][8][4];

    for (int blkIdx = bid - 32; blkIdx < nBlk; blkIdx += nAttn) {
        const int batch = blkIdx >> 6, blk = blkIdx & 63;

        // Mirror half: gelu(beta) broadcast rows (fire-and-forget stores)
        {
            float* mb = out + ((size_t)batch * 2 * SHALF + SHALF + (size_t)blk * 128) * DIM;
#pragma unroll
            for (int j = 0; j < 16; j++)
                *(float4*)(mb + (size_t)(mr0 + 8 * j) * DIM + mc4) = gb;
        }

        // Stage Mt into Sh via cp.async (background; overwritten in-place by P)
        {
            const char* M4 = (const char*)g_Mt;
            for (int i = tid; i < 2048; i += 256) {
                int r = i >> 4, c8 = (i & 15) << 3;
                cpasync16(sAddr + (r * LDH + c8) * 2, M4 + i * 16);
            }
            cpasync_commit();
        }

        // Load X block f32 -> fp16 smem (overlaps the Mt cp.async above)
        const float4* Xg4 =
            (const float4*)(x + ((size_t)batch * SHALF + (size_t)blk * 128) * DIM);
        for (int i = tid; i < 4096; i += 256) {
            int r = i >> 5, c4 = (i & 31) << 2;
            float4 v = Xg4[i];
            *(__half2*)(Xh + r * LDH + c4) = __floats2half2_rn(v.x, v.y);
            *(__half2*)(Xh + r * LDH + c4 + 2) = __floats2half2_rn(v.z, v.w);
        }
        cpasync_wait0();
        __syncthreads();   // Mt + X visible

        // G1: P = X @ Mt^T  (A=Xh, B=Sh plain); P overwrites Mt in Sh
        zero_acc(acc);
        gemm_h<0>(xAddr + aLane, sAddr + bpLane, acc);
        __syncthreads();                 // all warps done reading Mt
        store_c(Sh, acc, wm, wn, lane);
        __syncthreads();

        // G2: S = P @ X^T  (A=Sh, B=Xh plain), in place over P
        zero_acc(acc);
        gemm_h<0>(sAddr + aLane, xAddr + bpLane, acc);
        __syncthreads();
        store_c(Sh, acc, wm, wn, lane);
        __syncthreads();

        // Softmax: 2 threads per row, 64 cols each, fp16 in/out
        {
            const int row = tid >> 1, h = tid & 1;
            __half* rp = Sh + row * LDH + h * 64;
            float f[64];
#pragma unroll
            for (int i = 0; i < 8; i++) {
                uint4 v = *(uint4*)(rp + 8 * i);
                float2 p0 = __half22float2(*(__half2*)&v.x);
                float2 p1 = __half22float2(*(__half2*)&v.y);
                float2 p2 = __half22float2(*(__half2*)&v.z);
                float2 p3 = __half22float2(*(__half2*)&v.w);
                f[8 * i + 0] = p0.x; f[8 * i + 1] = p0.y;
                f[8 * i + 2] = p1.x; f[8 * i + 3] = p1.y;
                f[8 * i + 4] = p2.x; f[8 * i + 5] = p2.y;
                f[8 * i + 6] = p3.x; f[8 * i + 7] = p3.y;
            }
            float m = -1e30f;
#pragma unroll
            for (int i = 0; i < 64; i++) m = fmaxf(m, f[i]);
            m = fmaxf(m, __shfl_xor_sync(0xffffffffu, m, 1));
            float s = 0.f;
#pragma unroll
            for (int i = 0; i < 64; i++) { f[i] = __expf(f[i] - m); s += f[i]; }
            s += __shfl_xor_sync(0xffffffffu, s, 1);
            float inv = 1.0f / s;
#pragma unroll
            for (int i = 0; i < 8; i++) {
                uint4 v;
                *(__half2*)&v.x = __floats2half2_rn(f[8 * i + 0] * inv, f[8 * i + 1] * inv);
                *(__half2*)&v.y = __floats2half2_rn(f[8 * i + 2] * inv, f[8 * i + 3] * inv);
                *(__half2*)&v.z = __floats2half2_rn(f[8 * i + 4] * inv, f[8 * i + 5] * inv);
                *(__half2*)&v.w = __floats2half2_rn(f[8 * i + 6] * inv, f[8 * i + 7] * inv);
                *(uint4*)(rp + 8 * i) = v;
            }
        }
        __syncthreads();

        // G3: T = attn @ X  (A=Sh, B=Xh TRANS), in place over attn
        zero_acc(acc);
        gemm_h<1>(sAddr + aLane, xAddr + btLane, acc);
        __syncthreads();
        store_c(Sh, acc, wm, wn, lane);
        __syncthreads();

        // G4: H = T @ W2t^T (A=Sh, B=W2 plain), accumulators stay in registers
        zero_acc(acc);
        gemm_h<0>(sAddr + aLane, wAddr + bpLane, acc);

        // LN partials
#pragma unroll
        for (int mi = 0; mi < 2; mi++)
#pragma unroll
            for (int h = 0; h < 2; h++) {
                float s1 = 0.f, s2 = 0.f;
#pragma unroll
                for (int j = 0; j < 8; j++) {
                    float v0 = acc[mi][j][2 * h], v1 = acc[mi][j][2 * h + 1];
                    s1 += v0 + v1;
                    s2 += v0 * v0 + v1 * v1;
                }
                s1 += __shfl_xor_sync(0xffffffffu, s1, 1);
                s1 += __shfl_xor_sync(0xffffffffu, s1, 2);
                s2 += __shfl_xor_sync(0xffffffffu, s2, 1);
                s2 += __shfl_xor_sync(0xffffffffu, s2, 2);
                if ((lane & 3) == 0) {
                    int r = wm * 32 + mi * 16 + 8 * h + g4;
                    s_r1[r][wn] = s1;
                    s_r2[r][wn] = s2;
                }
            }
        __syncthreads();

        // Epilogue: LN + exact GELU from registers
        float* ob = out + ((size_t)batch * 2 * SHALF + (size_t)blk * 128) * DIM;
#pragma unroll
        for (int mi = 0; mi < 2; mi++)
#pragma unroll
            for (int h = 0; h < 2; h++) {
                const int r = wm * 32 + mi * 16 + 8 * h + g4;
                float s1 = s_r1[r][0] + s_r1[r][1];
                float s2 = s_r2[r][0] + s_r2[r][1];
                float mu = s1 * (1.0f / 128.0f);
                float var = s2 * (1.0f / 128.0f) - mu * mu;
                float rs = rsqrtf(var + 1e-5f);
                float* orow = ob + (size_t)r * DIM;
#pragma unroll
                for (int j = 0; j < 8; j++) {
                    const int c = wn * 64 + j * 8 + 2 * (lane & 3);
                    float2 o;
                    o.x = gelu_erf((acc[mi][j][2 * h] - mu) * rs * s_g[c] + s_b[c]);
                    o.y = gelu_erf((acc[mi][j][2 * h + 1] - mu) * rs * s_g[c + 1] + s_b[c + 1]);
                    *(float2*)(orow + c) = o;
                }
            }
        __syncthreads();   // Xh/Sh reused next iteration
    }
}

extern "C" void kernel_launch(void* const* d_in, const int* in_sizes, int n_in,
                              void* d_out, int out_size) {
    const float* x     = (const float*)d_in[0];
    const float* Wq    = (const float*)d_in[1];
    const float* Wk    = (const float*)d_in[2];
    const float* Wv    = (const float*)d_in[3];
    const float* Wo    = (const float*)d_in[4];
    const float* gamma = (const float*)d_in[5];
    const float* beta  = (const float*)d_in[6];
    float* out = (float*)d_out;

    int B = in_sizes[0] / (SHALF * DIM);  // 8
    int nBlk = B * 64;                    // 512

    int dev = 0, sms = 148;
    cudaGetDevice(&dev);
    cudaDeviceGetAttribute(&sms, cudaDevAttrMultiProcessorCount, dev);
    int nAttn = 2 * sms;                  // persistent CTAs (2/SM)
    if (nAttn > nBlk) nAttn = nBlk;

    const int smem_bytes = 3 * TILE_B;    // 104448
    cudaFuncSetAttribute(fused_kernel, cudaFuncAttributeMaxDynamicSharedMemorySize,
                         smem_bytes);
    fused_kernel<<<32 + nAttn, 256, smem_bytes>>>(x, Wq, Wk, Wv, Wo, gamma, beta,
                                                  out, nBlk, nAttn);
}

// round 16
// speedup vs baseline: 1.6945x; 1.0078x over previous
#include <cuda_runtime.h>
#include <cuda_fp16.h>
#include <cstdint>
#include <math.h>

#define DIM 128
#define SHALF 8192
#define LDH 136                 // halves per smem row (16B-phase conflict-free)
#define TILE_H (128 * LDH)      // halves per tile (17408)
#define TILE_B (TILE_H * 2)     // 34816 bytes per tile
#define LDF 132                 // f32 leading dim for prep

// Device scratch (no cudaMalloc allowed)
// g_Mt[n][k]  = sum_d Wk[n,d]*Wq[k,d]/sqrt(D)   (fp16)
// g_W2t[j][k] = sum_d Wv[k,d]*Wo[d,j]           (fp16)
__device__ __half g_Mt[DIM * DIM];
__device__ __half g_W2t[DIM * DIM];
__device__ unsigned g_flag;     // prep-done gate (monotone across launches)

__device__ __forceinline__ uint32_t smem_u32(const void* p) {
    uint32_t a;
    asm("{ .reg .u64 t; cvta.to.shared.u64 t, %1; cvt.u32.u64 %0, t; }" : "=r"(a) : "l"(p));
    return a;
}
__device__ __forceinline__ float gelu_erf(float y) {
    return 0.5f * y * (1.0f + erff(y * 0.70710678118654752440f));
}
__device__ __forceinline__ void cpasync16(uint32_t smem_dst, const void* gmem_src) {
    asm volatile("cp.async.cg.shared.global [%0], [%1], 16;"
                 :: "r"(smem_dst), "l"(gmem_src) : "memory");
}
__device__ __forceinline__ void cpasync_commit() {
    asm volatile("cp.async.commit_group;" ::: "memory");
}
__device__ __forceinline__ void cpasync_wait0() {
    asm volatile("cp.async.wait_group 0;" ::: "memory");
}
__device__ __forceinline__ void ldsm4(uint32_t r[4], uint32_t a) {
    asm volatile("ldmatrix.sync.aligned.m8n8.x4.shared.b16 {%0,%1,%2,%3}, [%4];"
                 : "=r"(r[0]), "=r"(r[1]), "=r"(r[2]), "=r"(r[3]) : "r"(a));
}
__device__ __forceinline__ void ldsm4t(uint32_t r[4], uint32_t a) {
    asm volatile("ldmatrix.sync.aligned.m8n8.x4.trans.shared.b16 {%0,%1,%2,%3}, [%4];"
                 : "=r"(r[0]), "=r"(r[1]), "=r"(r[2]), "=r"(r[3]) : "r"(a));
}
__device__ __forceinline__ void mma_h(float c[4], const uint32_t a[4],
                                      uint32_t b0, uint32_t b1) {
    asm volatile(
        "mma.sync.aligned.m16n8k16.row.col.f32.f16.f16.f32 "
        "{%0,%1,%2,%3}, {%4,%5,%6,%7}, {%8,%9}, {%0,%1,%2,%3};"
        : "+f"(c[0]), "+f"(c[1]), "+f"(c[2]), "+f"(c[3])
        : "r"(a[0]), "r"(a[1]), "r"(a[2]), "r"(a[3]), "r"(b0), "r"(b1));
}

// 128x128x128 fp16 GEMM, 8 warps (wm=wid&3: 32 rows; wn=wid>>2: 64 cols).
// BT=0: B is [n][k] row-major in smem (plain LDSM). BT=1: B is [k][n] (LDSM.trans).
template <int BT>
__device__ __forceinline__ void gemm_h(uint32_t aAddr, uint32_t bAddr,
                                       float acc[2][8][4]) {
#pragma unroll
    for (int kk = 0; kk < 8; kk++) {
        uint32_t a0[4], a1[4];
        ldsm4(a0, aAddr + kk * 32);
        ldsm4(a1, aAddr + 16 * LDH * 2 + kk * 32);
#pragma unroll
        for (int p = 0; p < 4; p++) {
            uint32_t b[4];
            if (BT) ldsm4t(b, bAddr + p * 32 + kk * (16 * LDH * 2));
            else    ldsm4 (b, bAddr + p * (16 * LDH * 2) + kk * 32);
            mma_h(acc[0][2 * p],     a0, b[0], b[1]);
            mma_h(acc[0][2 * p + 1], a0, b[2], b[3]);
            mma_h(acc[1][2 * p],     a1, b[0], b[1]);
            mma_h(acc[1][2 * p + 1], a1, b[2], b[3]);
        }
    }
}

__device__ __forceinline__ void zero_acc(float acc[2][8][4]) {
#pragma unroll
    for (int mi = 0; mi < 2; mi++)
#pragma unroll
        for (int j = 0; j < 8; j++)
#pragma unroll
            for (int e = 0; e < 4; e++) acc[mi][j][e] = 0.f;
}

// Store acc (fp16) to Ch at warp tile position.
__device__ __forceinline__ void store_c(__half* Ch, const float acc[2][8][4],
                                        int wm, int wn, int lane) {
    __half* base = Ch + (wm * 32 + (lane >> 2)) * LDH + wn * 64 + 2 * (lane & 3);
#pragma unroll
    for (int mi = 0; mi < 2; mi++)
#pragma unroll
        for (int j = 0; j < 8; j++) {
            *(__half2*)(base + mi * 16 * LDH + j * 8) =
                __floats2half2_rn(acc[mi][j][0], acc[mi][j][1]);
            *(__half2*)(base + mi * 16 * LDH + 8 * LDH + j * 8) =
                __floats2half2_rn(acc[mi][j][2], acc[mi][j][3]);
        }
}

// ---------------------------------------------------------------------------
// Fused kernel, 256 threads, 2 CTAs/SM. bid<32: prep. bid>=32: persistent
// attn CTA looping over blocks (stride nAttn).
// smem: Xh (X -> W2t after G3) | Wt (resident Mt) | Sh (P -> S -> attn -> T)
// 8 barriers/iteration; X load overlaps previous iteration's epilogue.
// ---------------------------------------------------------------------------
__global__ void __launch_bounds__(256, 2)
fused_kernel(const float* __restrict__ x,
             const float* __restrict__ Wq, const float* __restrict__ Wk,
             const float* __restrict__ Wv, const float* __restrict__ Wo,
             const float* __restrict__ gamma, const float* __restrict__ beta,
             float* __restrict__ out, int nBlk, int nAttn) {
    extern __shared__ __align__(16) char smraw[];
    const int tid = threadIdx.x, bid = blockIdx.x;

    // ===================== PREP CTAs =====================
    if (bid < 32) {
        float* BigT = (float*)smraw;            // [128][LDF]
        float* Sm = BigT + 128 * LDF;           // 1024 floats
        const bool modeM = bid < 16;
        const int strip = (bid & 15) * 8;

        if (modeM) {
            for (int i = tid; i < 16384; i += 256) {
                int k = i >> 7, d = i & 127;
                BigT[d * LDF + k] = Wq[i];                 // BigT[d][k] = Wq[k][d]
            }
            for (int i = tid; i < 1024; i += 256) {
                int n = i >> 7, d = i & 127;
                Sm[i] = Wk[(strip + n) * DIM + d];
            }
        } else {
            for (int i = tid; i < 16384; i += 256) {
                int k = i >> 7, d = i & 127;
                BigT[d * LDF + k] = Wv[i];                 // BigT[d][k] = Wv[k][d]
            }
            for (int i = tid; i < 1024; i += 256) {
                int d = i >> 3, j = i & 7;
                Sm[i] = Wo[d * DIM + strip + j];
            }
        }
        __syncthreads();

        const int row = tid >> 5, k0 = (tid & 31) << 2;
        float4 acc = make_float4(0.f, 0.f, 0.f, 0.f);
#pragma unroll 4
        for (int d = 0; d < 128; d++) {
            float s = modeM ? Sm[row * DIM + d] : Sm[d * 8 + row];
            float4 v = *(const float4*)(BigT + d * LDF + k0);
            acc.x += s * v.x; acc.y += s * v.y; acc.z += s * v.z; acc.w += s * v.w;
        }
        const float sc = modeM ? 0.08838834764831844055f : 1.0f;
        __half2 p0 = __floats2half2_rn(acc.x * sc, acc.y * sc);
        __half2 p1 = __floats2half2_rn(acc.z * sc, acc.w * sc);
        __half* dst = (modeM ? g_Mt : g_W2t) + (strip + row) * DIM + k0;
        *(__half2*)(dst) = p0;
        *(__half2*)(dst + 2) = p1;

        __syncthreads();
        if (tid == 0) {
            __threadfence();
            atomicAdd(&g_flag, 1u);
        }
        return;
    }

    // ===================== ATTN CTAs (persistent) =====================
    __half* Xh = (__half*)smraw;          // X [token][dim]; W2t after G3
    __half* Wt = Xh + TILE_H;             // Mt [n][k] (resident)
    __half* Sh = Wt + TILE_H;             // P -> S -> attn -> T
    __shared__ float s_r1[128][2], s_r2[128][2], s_g[DIM], s_b[DIM];

    const int lane = tid & 31, wid = tid >> 5;
    const int wm = wid & 3, wn = wid >> 2;
    const int g4 = lane >> 2;

    if (tid < DIM) { s_g[tid] = gamma[tid]; s_b[tid] = beta[tid]; }

    // Precompute gelu(beta) broadcast row chunk for mirror fill (registers)
    const int mc4 = (tid & 31) << 2, mr0 = tid >> 5;
    float4 gb;
    gb.x = gelu_erf(beta[mc4 + 0]);
    gb.y = gelu_erf(beta[mc4 + 1]);
    gb.z = gelu_erf(beta[mc4 + 2]);
    gb.w = gelu_erf(beta[mc4 + 3]);

    // Gate on prep (first launch only; values rewritten byte-identical after).
    if (tid == 0) {
        while (atomicAdd(&g_flag, 0u) < 32u) __nanosleep(128);
        __threadfence();
    }
    __syncthreads();

    const uint32_t xAddr = smem_u32(Xh), wAddr = smem_u32(Wt), sAddr = smem_u32(Sh);

    // Stage Mt once via cp.async (resident for the whole persistent loop)
    {
        const char* M4 = (const char*)g_Mt;
        for (int i = tid; i < 2048; i += 256) {
            int r = i >> 4, c8 = (i & 15) << 3;
            cpasync16(wAddr + (r * LDH + c8) * 2, M4 + i * 16);
        }
        cpasync_commit();
        cpasync_wait0();
    }

    // Lane-resolved LDSM byte addresses (loop-invariant)
    const uint32_t aLane = ((wm * 32 + (lane & 15)) * LDH + ((lane >> 4) << 3)) * 2;
    const uint32_t bpLane = (((lane & 7) + ((lane >> 4) << 3) + wn * 64) * LDH + (lane & 8)) * 2;
    const uint32_t btLane = ((lane & 15) * LDH + wn * 64 + ((lane >> 4) << 3)) * 2;

    float acc[2][8][4];

    for (int blkIdx = bid - 32; blkIdx < nBlk; blkIdx += nAttn) {
        const int batch = blkIdx >> 6, blk = blkIdx & 63;

        // Mirror half: gelu(beta) broadcast rows (fire-and-forget stores)
        {
            float* mb = out + ((size_t)batch * 2 * SHALF + SHALF + (size_t)blk * 128) * DIM;
#pragma unroll
            for (int j = 0; j < 16; j++)
                *(float4*)(mb + (size_t)(mr0 + 8 * j) * DIM + mc4) = gb;
        }

        // Load X block f32 -> fp16 smem (overlaps laggard warps' prior epilogue:
        // Xh is dead after the previous iteration's LN-partial barrier)
        const float4* Xg4 =
            (const float4*)(x + ((size_t)batch * SHALF + (size_t)blk * 128) * DIM);
        for (int i = tid; i < 4096; i += 256) {
            int r = i >> 5, c4 = (i & 31) << 2;
            float4 v = Xg4[i];
            *(__half2*)(Xh + r * LDH + c4) = __floats2half2_rn(v.x, v.y);
            *(__half2*)(Xh + r * LDH + c4 + 2) = __floats2half2_rn(v.z, v.w);
        }
        __syncthreads();   // (1) X visible; prior iter's Sh readers all done

        // G1: P = X @ Mt^T  (A=Xh, B=Wt plain, C->Sh — no aliasing)
        zero_acc(acc);
        gemm_h<0>(xAddr + aLane, wAddr + bpLane, acc);
        store_c(Sh, acc, wm, wn, lane);
        __syncthreads();   // (2) P visible

        // G2: S = P @ X^T  (A=Sh, B=Xh plain), in place over P
        zero_acc(acc);
        gemm_h<0>(sAddr + aLane, xAddr + bpLane, acc);
        __syncthreads();   // (3) P reads done
        store_c(Sh, acc, wm, wn, lane);
        __syncthreads();   // (4) S visible

        // Softmax: 2 threads per row, 64 cols each, fp16 in/out
        {
            const int row = tid >> 1, h = tid & 1;
            __half* rp = Sh + row * LDH + h * 64;
            float f[64];
#pragma unroll
            for (int i = 0; i < 8; i++) {
                uint4 v = *(uint4*)(rp + 8 * i);
                float2 p0 = __half22float2(*(__half2*)&v.x);
                float2 p1 = __half22float2(*(__half2*)&v.y);
                float2 p2 = __half22float2(*(__half2*)&v.z);
                float2 p3 = __half22float2(*(__half2*)&v.w);
                f[8 * i + 0] = p0.x; f[8 * i + 1] = p0.y;
                f[8 * i + 2] = p1.x; f[8 * i + 3] = p1.y;
                f[8 * i + 4] = p2.x; f[8 * i + 5] = p2.y;
                f[8 * i + 6] = p3.x; f[8 * i + 7] = p3.y;
            }
            float m = -1e30f;
#pragma unroll
            for (int i = 0; i < 64; i++) m = fmaxf(m, f[i]);
            m = fmaxf(m, __shfl_xor_sync(0xffffffffu, m, 1));
            float s = 0.f;
#pragma unroll
            for (int i = 0; i < 64; i++) { f[i] = __expf(f[i] - m); s += f[i]; }
            s += __shfl_xor_sync(0xffffffffu, s, 1);
            float inv = 1.0f / s;
#pragma unroll
            for (int i = 0; i < 8; i++) {
                uint4 v;
                *(__half2*)&v.x = __floats2half2_rn(f[8 * i + 0] * inv, f[8 * i + 1] * inv);
                *(__half2*)&v.y = __floats2half2_rn(f[8 * i + 2] * inv, f[8 * i + 3] * inv);
                *(__half2*)&v.z = __floats2half2_rn(f[8 * i + 4] * inv, f[8 * i + 5] * inv);
                *(__half2*)&v.w = __floats2half2_rn(f[8 * i + 6] * inv, f[8 * i + 7] * inv);
                *(uint4*)(rp + 8 * i) = v;
            }
        }
        __syncthreads();   // (5) attn visible

        // G3: T = attn @ X  (A=Sh, B=Xh TRANS), in place over attn
        zero_acc(acc);
        gemm_h<1>(sAddr + aLane, xAddr + btLane, acc);
        __syncthreads();   // (6) attn + Xh reads done -> Xh dead

        // Store T; stage W2t into Xh via cp.async (hidden under the store)
        {
            const char* W4 = (const char*)g_W2t;
            for (int i = tid; i < 2048; i += 256) {
                int r = i >> 4, c8 = (i & 15) << 3;
                cpasync16(xAddr + (r * LDH + c8) * 2, W4 + i * 16);
            }
            cpasync_commit();
        }
        store_c(Sh, acc, wm, wn, lane);
        cpasync_wait0();
        __syncthreads();   // (7) T + W2t visible

        // G4: H = T @ W2t^T (A=Sh, B=Xh plain), accumulators stay in registers
        zero_acc(acc);
        gemm_h<0>(sAddr + aLane, xAddr + bpLane, acc);

        // LN partials
#pragma unroll
        for (int mi = 0; mi < 2; mi++)
#pragma unroll
            for (int h = 0; h < 2; h++) {
                float s1 = 0.f, s2 = 0.f;
#pragma unroll
                for (int j = 0; j < 8; j++) {
                    float v0 = acc[mi][j][2 * h], v1 = acc[mi][j][2 * h + 1];
                    s1 += v0 + v1;
                    s2 += v0 * v0 + v1 * v1;
                }
                s1 += __shfl_xor_sync(0xffffffffu, s1, 1);
                s1 += __shfl_xor_sync(0xffffffffu, s1, 2);
                s2 += __shfl_xor_sync(0xffffffffu, s2, 1);
                s2 += __shfl_xor_sync(0xffffffffu, s2, 2);
                if ((lane & 3) == 0) {
                    int r = wm * 32 + mi * 16 + 8 * h + g4;
                    s_r1[r][wn] = s1;
                    s_r2[r][wn] = s2;
                }
            }
        __syncthreads();   // (8) partials visible; Xh/Sh now dead to all warps

        // Epilogue: LN + exact GELU from registers (no trailing barrier:
        // next iteration's X load may start in faster warps immediately)
        float* ob = out + ((size_t)batch * 2 * SHALF + (size_t)blk * 128) * DIM;
#pragma unroll
        for (int mi = 0; mi < 2; mi++)
#pragma unroll
            for (int h = 0; h < 2; h++) {
                const int r = wm * 32 + mi * 16 + 8 * h + g4;
                float s1 = s_r1[r][0] + s_r1[r][1];
                float s2 = s_r2[r][0] + s_r2[r][1];
                float mu = s1 * (1.0f / 128.0f);
                float var = s2 * (1.0f / 128.0f) - mu * mu;
                float rs = rsqrtf(var + 1e-5f);
                float* orow = ob + (size_t)r * DIM;
#pragma unroll
                for (int j = 0; j < 8; j++) {
                    const int c = wn * 64 + j * 8 + 2 * (lane & 3);
                    float2 o;
                    o.x = gelu_erf((acc[mi][j][2 * h] - mu) * rs * s_g[c] + s_b[c]);
                    o.y = gelu_erf((acc[mi][j][2 * h + 1] - mu) * rs * s_g[c + 1] + s_b[c + 1]);
                    *(float2*)(orow + c) = o;
                }
            }
    }
}

extern "C" void kernel_launch(void* const* d_in, const int* in_sizes, int n_in,
                              void* d_out, int out_size) {
    const float* x     = (const float*)d_in[0];
    const float* Wq    = (const float*)d_in[1];
    const float* Wk    = (const float*)d_in[2];
    const float* Wv    = (const float*)d_in[3];
    const float* Wo    = (const float*)d_in[4];
    const float* gamma = (const float*)d_in[5];
    const float* beta  = (const float*)d_in[6];
    float* out = (float*)d_out;

    int B = in_sizes[0] / (SHALF * DIM);  // 8
    int nBlk = B * 64;                    // 512

    int dev = 0, sms = 148;
    cudaGetDevice(&dev);
    cudaDeviceGetAttribute(&sms, cudaDevAttrMultiProcessorCount, dev);
    int nAttn = 2 * sms;                  // persistent CTAs (2/SM)
    if (nAttn > nBlk) nAttn = nBlk;

    const int smem_bytes = 3 * TILE_B;    // 104448
    cudaFuncSetAttribute(fused_kernel, cudaFuncAttributeMaxDynamicSharedMemorySize,
                         smem_bytes);
    fused_kernel<<<32 + nAttn, 256, smem_bytes>>>(x, Wq, Wk, Wv, Wo, gamma, beta,
                                                  out, nBlk, nAttn);
}